// round 15
// baseline (speedup 1.0000x reference)
#include <cuda_runtime.h>

#define NTOK 4096
#define DIM  1024
#define HDIM 4096
#define NE   8

#define TM 128
#define TN 128
#define TK 16
#define SSTRIDE 132   // smem row stride (floats): 528B, 16B-aligned, not %128

__device__ int   g_counts[NE];
__device__ int   g_tlist[NE * NTOK];
__device__ float g_h[(size_t)NTOK * HDIM];   // relu(x@fc)^2 scratch, 64 MB (proven-safe)

// ---------------------------------------------------------------------------
__global__ void init_counts_kernel() {
    if (threadIdx.x < NE) g_counts[threadIdx.x] = 0;
}

// One warp per token: fp32 logits, first-max argmax (matches jnp.argmax),
// atomic compaction into per-expert token lists.
__global__ void router_kernel(const float* __restrict__ x,
                              const float* __restrict__ rw) {
    int warp = (blockIdx.x * blockDim.x + threadIdx.x) >> 5;
    int lane = threadIdx.x & 31;
    if (warp >= NTOK) return;
    const float* xr = x + (size_t)warp * DIM;
    float best = -1e30f;
    int bestE = 0;
#pragma unroll
    for (int e = 0; e < NE; e++) {
        const float* wr = rw + e * DIM;
        float p = 0.f;
        for (int k = lane; k < DIM; k += 32) p += xr[k] * wr[k];
#pragma unroll
        for (int o = 16; o; o >>= 1) p += __shfl_xor_sync(0xffffffffu, p, o);
        if (p > best) { best = p; bestE = e; }   // strict > keeps earliest index
    }
    if (lane == 0) {
        int slot = atomicAdd(&g_counts[bestE], 1);
        g_tlist[bestE * NTOK + slot] = warp;
    }
}

// ---------------------------------------------------------------------------
// Gathered grouped fp32 SIMT GEMM, R1 loop structure (single buffer,
// load -> sync -> compute -> sync), 128x128x16 tile, 8x8 outputs/thread.
// smem: As[k][m], Bs[k][n], stride SSTRIDE.
// BTRANS=true : B elem (k,n) at Bq[k*HDIM+n]  (GEMM1, fc)   -> direct row copy
// BTRANS=false: B elem (n,k) at Bq[n*HDIM+k]  (GEMM2, proj) -> transpose on store
template <int KTOT, bool RELU2, bool BTRANS>
__global__ __launch_bounds__(256) void gemm_simt(
    const float* __restrict__ Abase, int astride,
    const float* __restrict__ Bbase,
    float* __restrict__ Obase, int ostride)
{
    __shared__ float As[TK][SSTRIDE];
    __shared__ float Bs[TK][SSTRIDE];
    __shared__ int   toks[TM];

    const int e = blockIdx.z;
    const int count = g_counts[e];
    const int m0 = blockIdx.y * TM;
    if (m0 >= count) return;
    const int n0 = blockIdx.x * TN;

    const int tid = threadIdx.x;
    if (tid < TM) {
        int mg = m0 + tid;
        toks[tid] = (mg < count) ? g_tlist[e * NTOK + mg] : -1;
    }
    __syncthreads();

    const float* Bq = Bbase + (size_t)e * DIM * HDIM;

    // ---- A loader: 128 rows x 16 k = 512 float4; 2 slots (R1 algebra) ----
    const float* aptr[2];
    int arow[2], akq[2];
#pragma unroll
    for (int q = 0; q < 2; q++) {
        int idx = q * 256 + tid;
        arow[q] = idx >> 2;                 // 0..127
        akq[q]  = (idx & 3) * 4;            // 0,4,8,12
        int tok = toks[arow[q]];
        aptr[q] = (tok >= 0) ? (Abase + (size_t)tok * astride + akq[q]) : nullptr;
    }
    // ---- B loader: 512 float4; 2 slots ----
    const float* bptr[2];
    int bkk[2], bn4[2], brow[2], bkq[2];
#pragma unroll
    for (int q = 0; q < 2; q++) {
        int idx = q * 256 + tid;
        if (BTRANS) {                       // tile [k=16][n=128]
            bkk[q] = idx >> 5;              // 0..15
            bn4[q] = (idx & 31) * 4;        // 0..124
            bptr[q] = Bq + (size_t)bkk[q] * HDIM + n0 + bn4[q];
        } else {                            // src [n][k] -> transpose on store
            brow[q] = idx >> 2;             // 0..127
            bkq[q]  = (idx & 3) * 4;        // 0,4,8,12
            bptr[q] = Bq + (size_t)(n0 + brow[q]) * HDIM + bkq[q];
        }
    }

    const int tx = tid & 15;                // cols tx*8..+7
    const int ty = tid >> 4;                // rows ty*8..+7

    float acc[8][8];
#pragma unroll
    for (int i = 0; i < 8; i++)
#pragma unroll
        for (int j = 0; j < 8; j++) acc[i][j] = 0.f;

    for (int k0 = 0; k0 < KTOT; k0 += TK) {
        // ---- load tiles (R1 pattern: straight into smem, then sync) ----
#pragma unroll
        for (int q = 0; q < 2; q++) {
            float4 av = make_float4(0.f, 0.f, 0.f, 0.f);
            if (aptr[q]) av = *(const float4*)(aptr[q] + k0);
            As[akq[q] + 0][arow[q]] = av.x;
            As[akq[q] + 1][arow[q]] = av.y;
            As[akq[q] + 2][arow[q]] = av.z;
            As[akq[q] + 3][arow[q]] = av.w;

            if (BTRANS) {
                float4 bv = *(const float4*)(bptr[q] + (size_t)k0 * HDIM);
                *(float4*)&Bs[bkk[q]][bn4[q]] = bv;
            } else {
                float4 bv = *(const float4*)(bptr[q] + k0);
                Bs[bkq[q] + 0][brow[q]] = bv.x;
                Bs[bkq[q] + 1][brow[q]] = bv.y;
                Bs[bkq[q] + 2][brow[q]] = bv.z;
                Bs[bkq[q] + 3][brow[q]] = bv.w;
            }
        }
        __syncthreads();

#pragma unroll
        for (int kk = 0; kk < TK; kk++) {
            float4 a0 = *(const float4*)&As[kk][ty * 8];
            float4 a1 = *(const float4*)&As[kk][ty * 8 + 4];
            float4 b0 = *(const float4*)&Bs[kk][tx * 8];
            float4 b1 = *(const float4*)&Bs[kk][tx * 8 + 4];
            float ar[8] = {a0.x, a0.y, a0.z, a0.w, a1.x, a1.y, a1.z, a1.w};
            float br[8] = {b0.x, b0.y, b0.z, b0.w, b1.x, b1.y, b1.z, b1.w};
#pragma unroll
            for (int i = 0; i < 8; i++)
#pragma unroll
                for (int j = 0; j < 8; j++) acc[i][j] += ar[i] * br[j];
        }
        __syncthreads();
    }

    // ---- epilogue: rows ty*8..+7, cols n0 + tx*8..+7 ----
#pragma unroll
    for (int i = 0; i < 8; i++) {
        int tok = toks[ty * 8 + i];
        if (tok < 0) continue;
        float v[8];
#pragma unroll
        for (int j = 0; j < 8; j++) {
            v[j] = acc[i][j];
            if (RELU2) { v[j] = fmaxf(v[j], 0.f); v[j] *= v[j]; }
        }
        float* o = Obase + (size_t)tok * ostride + n0 + tx * 8;
        *(float4*)(o)     = make_float4(v[0], v[1], v[2], v[3]);
        *(float4*)(o + 4) = make_float4(v[4], v[5], v[6], v[7]);
    }
}

// ---------------------------------------------------------------------------
extern "C" void kernel_launch(void* const* d_in, const int* in_sizes, int n_in,
                              void* d_out, int out_size) {
    const float* x    = (const float*)d_in[0];
    const float* rw   = (const float*)d_in[1];
    const float* fc   = (const float*)d_in[2];
    const float* proj = (const float*)d_in[3];
    float* out = (float*)d_out;

    init_counts_kernel<<<1, 32>>>();
    router_kernel<<<(NTOK * 32) / 256, 256>>>(x, rw);

    dim3 g1(HDIM / TN, NTOK / TM, NE);   // 32 x 32 x 8, most blocks early-exit
    gemm_simt<DIM, true, true><<<g1, 256>>>(x, DIM, fc, g_h, HDIM);

    dim3 g2(DIM / TN, NTOK / TM, NE);    // 8 x 32 x 8
    gemm_simt<HDIM, false, false><<<g2, 256>>>(g_h, HDIM, proj, out, DIM);
}

// round 16
// speedup vs baseline: 1.8390x; 1.8390x over previous
#include <cuda_runtime.h>

#define NTOK 4096
#define DIM  1024
#define HDIM 4096
#define NE   8

#define TM 64
#define TN 64
#define TK 32
#define SSTRIDE 68   // smem row stride (floats): keeps 16B alignment, reduces conflicts

__device__ int   g_counts[NE];
__device__ int   g_tlist[NE * NTOK];
__device__ float g_h[(size_t)NTOK * HDIM];   // relu(x@fc)^2 scratch, 64 MB

// ---------------------------------------------------------------------------
__global__ void init_counts_kernel() {
    if (threadIdx.x < NE) g_counts[threadIdx.x] = 0;
}

// One warp per token: fp32 logits, first-max argmax (matches jnp.argmax),
// atomic compaction into per-expert token lists.
__global__ void router_kernel(const float* __restrict__ x,
                              const float* __restrict__ rw) {
    int warp = (blockIdx.x * blockDim.x + threadIdx.x) >> 5;
    int lane = threadIdx.x & 31;
    if (warp >= NTOK) return;
    const float* xr = x + (size_t)warp * DIM;
    float best = -1e30f;
    int bestE = 0;
#pragma unroll
    for (int e = 0; e < NE; e++) {
        const float* wr = rw + e * DIM;
        float p = 0.f;
        for (int k = lane; k < DIM; k += 32) p += xr[k] * wr[k];
#pragma unroll
        for (int o = 16; o; o >>= 1) p += __shfl_xor_sync(0xffffffffu, p, o);
        if (p > best) { best = p; bestE = e; }   // strict > keeps earliest index
    }
    if (lane == 0) {
        int slot = atomicAdd(&g_counts[bestE], 1);
        g_tlist[bestE * NTOK + slot] = warp;
    }
}

// ---------------------------------------------------------------------------
// GEMM1: for expert e, h[token, n] = relu( x[token,:] @ fc_e[:, n] )^2
// fc layout [E, D, HD] (n contiguous). A rows gathered via token list.
// R1 structure, TK=32: tile loads use 2 slots of 256 threads each.
__global__ __launch_bounds__(256) void gemm1_kernel(const float* __restrict__ x,
                                                    const float* __restrict__ fc) {
    const int e = blockIdx.z;
    const int count = g_counts[e];
    const int m0 = blockIdx.y * TM;
    if (m0 >= count) return;
    const int n0 = blockIdx.x * TN;

    __shared__ float As[TK][SSTRIDE];   // transposed: As[k][row]
    __shared__ float Bs[TK][SSTRIDE];   // Bs[k][col]
    __shared__ int   toks[TM];

    const int tid = threadIdx.x;
    const int tx = tid & 15;            // 16 col groups
    const int ty = tid >> 4;            // 16 row groups

    if (tid < TM) {
        int mg = m0 + tid;
        toks[tid] = (mg < count) ? g_tlist[e * NTOK + mg] : -1;
    }
    __syncthreads();

    // A: 64 rows x 32 k = 512 float4, 2 slots: row = idx>>3, kq = (idx&7)*4
    int a_row[2], a_k[2], tokA[2];
#pragma unroll
    for (int q = 0; q < 2; q++) {
        int idx = q * 256 + tid;
        a_row[q] = idx >> 3;
        a_k[q]   = (idx & 7) * 4;
        tokA[q]  = toks[a_row[q]];
    }
    // B: 32 k x 64 n = 512 float4, 2 slots: kk = idx>>4, n4 = (idx&15)*4
    int b_k[2], b_n[2];
#pragma unroll
    for (int q = 0; q < 2; q++) {
        int idx = q * 256 + tid;
        b_k[q] = idx >> 4;
        b_n[q] = (idx & 15) * 4;
    }

    const float* fce = fc + (size_t)e * DIM * HDIM;

    float acc[4][4];
#pragma unroll
    for (int i = 0; i < 4; i++)
#pragma unroll
        for (int j = 0; j < 4; j++) acc[i][j] = 0.f;

    for (int k0 = 0; k0 < DIM; k0 += TK) {
#pragma unroll
        for (int q = 0; q < 2; q++) {
            float4 av = make_float4(0.f, 0.f, 0.f, 0.f);
            if (tokA[q] >= 0)
                av = *(const float4*)(x + (size_t)tokA[q] * DIM + k0 + a_k[q]);
            As[a_k[q] + 0][a_row[q]] = av.x;
            As[a_k[q] + 1][a_row[q]] = av.y;
            As[a_k[q] + 2][a_row[q]] = av.z;
            As[a_k[q] + 3][a_row[q]] = av.w;

            float4 bv = *(const float4*)(fce + (size_t)(k0 + b_k[q]) * HDIM + n0 + b_n[q]);
            *(float4*)&Bs[b_k[q]][b_n[q]] = bv;
        }
        __syncthreads();

#pragma unroll
        for (int kk = 0; kk < TK; kk++) {
            float4 a = *(const float4*)&As[kk][ty * 4];
            float4 b = *(const float4*)&Bs[kk][tx * 4];
            acc[0][0] += a.x * b.x; acc[0][1] += a.x * b.y; acc[0][2] += a.x * b.z; acc[0][3] += a.x * b.w;
            acc[1][0] += a.y * b.x; acc[1][1] += a.y * b.y; acc[1][2] += a.y * b.z; acc[1][3] += a.y * b.w;
            acc[2][0] += a.z * b.x; acc[2][1] += a.z * b.y; acc[2][2] += a.z * b.z; acc[2][3] += a.z * b.w;
            acc[3][0] += a.w * b.x; acc[3][1] += a.w * b.y; acc[3][2] += a.w * b.z; acc[3][3] += a.w * b.w;
        }
        __syncthreads();
    }

#pragma unroll
    for (int i = 0; i < 4; i++) {
        int r = ty * 4 + i;
        int tok = toks[r];
        if (tok < 0) continue;
        float4 v;
        float t0 = fmaxf(acc[i][0], 0.f);
        float t1 = fmaxf(acc[i][1], 0.f);
        float t2 = fmaxf(acc[i][2], 0.f);
        float t3 = fmaxf(acc[i][3], 0.f);
        v.x = t0 * t0; v.y = t1 * t1; v.z = t2 * t2; v.w = t3 * t3;
        *(float4*)(g_h + (size_t)tok * HDIM + n0 + tx * 4) = v;
    }
}

// ---------------------------------------------------------------------------
// GEMM2: out[token, d] = h[token,:] @ proj_e[d, :]   (proj layout [E, D, HD], k contiguous)
__global__ __launch_bounds__(256) void gemm2_kernel(const float* __restrict__ proj,
                                                    float* __restrict__ out) {
    const int e = blockIdx.z;
    const int count = g_counts[e];
    const int m0 = blockIdx.y * TM;
    if (m0 >= count) return;
    const int n0 = blockIdx.x * TN;

    __shared__ float As[TK][SSTRIDE];
    __shared__ float Bs[TK][SSTRIDE];
    __shared__ int   toks[TM];

    const int tid = threadIdx.x;
    const int tx = tid & 15;
    const int ty = tid >> 4;

    if (tid < TM) {
        int mg = m0 + tid;
        toks[tid] = (mg < count) ? g_tlist[e * NTOK + mg] : -1;
    }
    __syncthreads();

    // A: 64 rows x 32 k, 2 slots (same as gemm1)
    int a_row[2], a_k[2], tokA[2];
#pragma unroll
    for (int q = 0; q < 2; q++) {
        int idx = q * 256 + tid;
        a_row[q] = idx >> 3;
        a_k[q]   = (idx & 7) * 4;
        tokA[q]  = toks[a_row[q]];
    }
    // B: 64 n-rows x 8 kq groups (k contiguous in src) -> transpose into smem
    int b_n[2], b_k[2];
#pragma unroll
    for (int q = 0; q < 2; q++) {
        int idx = q * 256 + tid;
        b_n[q] = idx >> 3;              // 0..63
        b_k[q] = (idx & 7) * 4;         // 0..28
    }

    const float* pe = proj + (size_t)e * DIM * HDIM;

    float acc[4][4];
#pragma unroll
    for (int i = 0; i < 4; i++)
#pragma unroll
        for (int j = 0; j < 4; j++) acc[i][j] = 0.f;

    for (int k0 = 0; k0 < HDIM; k0 += TK) {
#pragma unroll
        for (int q = 0; q < 2; q++) {
            float4 av = make_float4(0.f, 0.f, 0.f, 0.f);
            if (tokA[q] >= 0)
                av = *(const float4*)(g_h + (size_t)tokA[q] * HDIM + k0 + a_k[q]);
            As[a_k[q] + 0][a_row[q]] = av.x;
            As[a_k[q] + 1][a_row[q]] = av.y;
            As[a_k[q] + 2][a_row[q]] = av.z;
            As[a_k[q] + 3][a_row[q]] = av.w;

            float4 bv = *(const float4*)(pe + (size_t)(n0 + b_n[q]) * HDIM + k0 + b_k[q]);
            Bs[b_k[q] + 0][b_n[q]] = bv.x;
            Bs[b_k[q] + 1][b_n[q]] = bv.y;
            Bs[b_k[q] + 2][b_n[q]] = bv.z;
            Bs[b_k[q] + 3][b_n[q]] = bv.w;
        }
        __syncthreads();

#pragma unroll
        for (int kk = 0; kk < TK; kk++) {
            float4 a = *(const float4*)&As[kk][ty * 4];
            float4 b = *(const float4*)&Bs[kk][tx * 4];
            acc[0][0] += a.x * b.x; acc[0][1] += a.x * b.y; acc[0][2] += a.x * b.z; acc[0][3] += a.x * b.w;
            acc[1][0] += a.y * b.x; acc[1][1] += a.y * b.y; acc[1][2] += a.y * b.z; acc[1][3] += a.y * b.w;
            acc[2][0] += a.z * b.x; acc[2][1] += a.z * b.y; acc[2][2] += a.z * b.z; acc[2][3] += a.z * b.w;
            acc[3][0] += a.w * b.x; acc[3][1] += a.w * b.y; acc[3][2] += a.w * b.z; acc[3][3] += a.w * b.w;
        }
        __syncthreads();
    }

#pragma unroll
    for (int i = 0; i < 4; i++) {
        int r = ty * 4 + i;
        int tok = toks[r];
        if (tok < 0) continue;
        float4 v = make_float4(acc[i][0], acc[i][1], acc[i][2], acc[i][3]);
        *(float4*)(out + (size_t)tok * DIM + n0 + tx * 4) = v;
    }
}

// ---------------------------------------------------------------------------
extern "C" void kernel_launch(void* const* d_in, const int* in_sizes, int n_in,
                              void* d_out, int out_size) {
    const float* x    = (const float*)d_in[0];
    const float* rw   = (const float*)d_in[1];
    const float* fc   = (const float*)d_in[2];
    const float* proj = (const float*)d_in[3];
    float* out = (float*)d_out;

    init_counts_kernel<<<1, 32>>>();
    router_kernel<<<(NTOK * 32) / 256, 256>>>(x, rw);

    dim3 g1(HDIM / TN, NTOK / TM, NE);   // 64 x 64 x 8, most blocks early-exit
    gemm1_kernel<<<g1, 256>>>(x, fc);

    dim3 g2(DIM / TN, NTOK / TM, NE);    // 16 x 64 x 8
    gemm2_kernel<<<g2, 256>>>(proj, out);
}

// round 17
// speedup vs baseline: 2.0430x; 1.1109x over previous
#include <cuda_runtime.h>

#define NTOK 4096
#define DIM  1024
#define HDIM 4096
#define NE   8

#define TM 128
#define TN 64
#define TK 16
#define SSTRA 132   // As row stride (floats): 128 rows + pad
#define SSTRB 68    // Bs row stride (floats): 64 cols + pad

__device__ int   g_counts[NE];
__device__ int   g_tlist[NE * NTOK];
__device__ float g_h[(size_t)NTOK * HDIM];   // relu(x@fc)^2 scratch, 64 MB

// ---------------------------------------------------------------------------
__global__ void init_counts_kernel() {
    if (threadIdx.x < NE) g_counts[threadIdx.x] = 0;
}

// One warp per token: fp32 logits, first-max argmax (matches jnp.argmax),
// atomic compaction into per-expert token lists.
__global__ void router_kernel(const float* __restrict__ x,
                              const float* __restrict__ rw) {
    int warp = (blockIdx.x * blockDim.x + threadIdx.x) >> 5;
    int lane = threadIdx.x & 31;
    if (warp >= NTOK) return;
    const float* xr = x + (size_t)warp * DIM;
    float best = -1e30f;
    int bestE = 0;
#pragma unroll
    for (int e = 0; e < NE; e++) {
        const float* wr = rw + e * DIM;
        float p = 0.f;
        for (int k = lane; k < DIM; k += 32) p += xr[k] * wr[k];
#pragma unroll
        for (int o = 16; o; o >>= 1) p += __shfl_xor_sync(0xffffffffu, p, o);
        if (p > best) { best = p; bestE = e; }   // strict > keeps earliest index
    }
    if (lane == 0) {
        int slot = atomicAdd(&g_counts[bestE], 1);
        g_tlist[bestE * NTOK + slot] = warp;
    }
}

// ---------------------------------------------------------------------------
// GEMM1: for expert e, h[token, n] = relu( x[token,:] @ fc_e[:, n] )^2
// fc layout [E, D, HD] (n contiguous). A rows gathered via token list.
// R14 structure; TM=128 with 8x4 outputs/thread.
__global__ __launch_bounds__(256) void gemm1_kernel(const float* __restrict__ x,
                                                    const float* __restrict__ fc) {
    const int e = blockIdx.z;
    const int count = g_counts[e];
    const int m0 = blockIdx.y * TM;
    if (m0 >= count) return;
    const int n0 = blockIdx.x * TN;

    __shared__ float As[TK][SSTRA];   // transposed: As[k][row]
    __shared__ float Bs[TK][SSTRB];   // Bs[k][col]
    __shared__ int   toks[TM];

    const int tid = threadIdx.x;
    const int tx = tid & 15;            // 16 col groups (cols tx*4..+3)
    const int ty = tid >> 4;            // 16 row groups (rows ty*8..+7)

    if (tid < TM) {
        int mg = m0 + tid;
        toks[tid] = (mg < count) ? g_tlist[e * NTOK + mg] : -1;
    }
    __syncthreads();

    // A: 128 rows x 16 k = 512 float4, 2 slots: row = idx>>2, kq = (idx&3)*4
    int a_row[2], a_k[2], tokA[2];
#pragma unroll
    for (int q = 0; q < 2; q++) {
        int idx = q * 256 + tid;
        a_row[q] = idx >> 2;
        a_k[q]   = (idx & 3) * 4;
        tokA[q]  = toks[a_row[q]];
    }
    // B: k = tid/16, ng = tid%16 -> n = ng*4 (float4)   (R14 verbatim)
    const int b_k = tid >> 4;
    const int b_n = (tid & 15) * 4;

    const float* fce = fc + (size_t)e * DIM * HDIM;

    float acc[8][4];
#pragma unroll
    for (int i = 0; i < 8; i++)
#pragma unroll
        for (int j = 0; j < 4; j++) acc[i][j] = 0.f;

    for (int k0 = 0; k0 < DIM; k0 += TK) {
        // load A tile (gathered, transposed into smem), 2 slots
#pragma unroll
        for (int q = 0; q < 2; q++) {
            float4 av = make_float4(0.f, 0.f, 0.f, 0.f);
            if (tokA[q] >= 0)
                av = *(const float4*)(x + (size_t)tokA[q] * DIM + k0 + a_k[q]);
            As[a_k[q] + 0][a_row[q]] = av.x;
            As[a_k[q] + 1][a_row[q]] = av.y;
            As[a_k[q] + 2][a_row[q]] = av.z;
            As[a_k[q] + 3][a_row[q]] = av.w;
        }
        // load B tile (R14 verbatim)
        float4 bv = *(const float4*)(fce + (size_t)(k0 + b_k) * HDIM + n0 + b_n);
        *(float4*)&Bs[b_k][b_n] = bv;
        __syncthreads();

#pragma unroll
        for (int kk = 0; kk < TK; kk++) {
            float4 a0 = *(const float4*)&As[kk][ty * 8];
            float4 a1 = *(const float4*)&As[kk][ty * 8 + 4];
            float4 b  = *(const float4*)&Bs[kk][tx * 4];
            acc[0][0] += a0.x * b.x; acc[0][1] += a0.x * b.y; acc[0][2] += a0.x * b.z; acc[0][3] += a0.x * b.w;
            acc[1][0] += a0.y * b.x; acc[1][1] += a0.y * b.y; acc[1][2] += a0.y * b.z; acc[1][3] += a0.y * b.w;
            acc[2][0] += a0.z * b.x; acc[2][1] += a0.z * b.y; acc[2][2] += a0.z * b.z; acc[2][3] += a0.z * b.w;
            acc[3][0] += a0.w * b.x; acc[3][1] += a0.w * b.y; acc[3][2] += a0.w * b.z; acc[3][3] += a0.w * b.w;
            acc[4][0] += a1.x * b.x; acc[4][1] += a1.x * b.y; acc[4][2] += a1.x * b.z; acc[4][3] += a1.x * b.w;
            acc[5][0] += a1.y * b.x; acc[5][1] += a1.y * b.y; acc[5][2] += a1.y * b.z; acc[5][3] += a1.y * b.w;
            acc[6][0] += a1.z * b.x; acc[6][1] += a1.z * b.y; acc[6][2] += a1.z * b.z; acc[6][3] += a1.z * b.w;
            acc[7][0] += a1.w * b.x; acc[7][1] += a1.w * b.y; acc[7][2] += a1.w * b.z; acc[7][3] += a1.w * b.w;
        }
        __syncthreads();
    }

#pragma unroll
    for (int i = 0; i < 8; i++) {
        int r = ty * 8 + i;
        int tok = toks[r];
        if (tok < 0) continue;
        float4 v;
        float t0 = fmaxf(acc[i][0], 0.f);
        float t1 = fmaxf(acc[i][1], 0.f);
        float t2 = fmaxf(acc[i][2], 0.f);
        float t3 = fmaxf(acc[i][3], 0.f);
        v.x = t0 * t0; v.y = t1 * t1; v.z = t2 * t2; v.w = t3 * t3;
        *(float4*)(g_h + (size_t)tok * HDIM + n0 + tx * 4) = v;
    }
}

// ---------------------------------------------------------------------------
// GEMM2: out[token, d] = h[token,:] @ proj_e[d, :]   (proj layout [E, D, HD], k contiguous)
__global__ __launch_bounds__(256) void gemm2_kernel(const float* __restrict__ proj,
                                                    float* __restrict__ out) {
    const int e = blockIdx.z;
    const int count = g_counts[e];
    const int m0 = blockIdx.y * TM;
    if (m0 >= count) return;
    const int n0 = blockIdx.x * TN;

    __shared__ float As[TK][SSTRA];
    __shared__ float Bs[TK][SSTRB];
    __shared__ int   toks[TM];

    const int tid = threadIdx.x;
    const int tx = tid & 15;
    const int ty = tid >> 4;

    if (tid < TM) {
        int mg = m0 + tid;
        toks[tid] = (mg < count) ? g_tlist[e * NTOK + mg] : -1;
    }
    __syncthreads();

    int a_row[2], a_k[2], tokA[2];
#pragma unroll
    for (int q = 0; q < 2; q++) {
        int idx = q * 256 + tid;
        a_row[q] = idx >> 2;
        a_k[q]   = (idx & 3) * 4;
        tokA[q]  = toks[a_row[q]];
    }
    // B: n-major rows, k contiguous -> load [n, k..k+3], transpose (R14 verbatim)
    const int b_n  = tid >> 2;          // 64 n values
    const int b_k  = (tid & 3) * 4;     // 4 k groups

    const float* pe = proj + (size_t)e * DIM * HDIM;

    float acc[8][4];
#pragma unroll
    for (int i = 0; i < 8; i++)
#pragma unroll
        for (int j = 0; j < 4; j++) acc[i][j] = 0.f;

    for (int k0 = 0; k0 < HDIM; k0 += TK) {
#pragma unroll
        for (int q = 0; q < 2; q++) {
            float4 av = make_float4(0.f, 0.f, 0.f, 0.f);
            if (tokA[q] >= 0)
                av = *(const float4*)(g_h + (size_t)tokA[q] * HDIM + k0 + a_k[q]);
            As[a_k[q] + 0][a_row[q]] = av.x;
            As[a_k[q] + 1][a_row[q]] = av.y;
            As[a_k[q] + 2][a_row[q]] = av.z;
            As[a_k[q] + 3][a_row[q]] = av.w;
        }
        float4 bv = *(const float4*)(pe + (size_t)(n0 + b_n) * HDIM + k0 + b_k);
        Bs[b_k + 0][b_n] = bv.x;
        Bs[b_k + 1][b_n] = bv.y;
        Bs[b_k + 2][b_n] = bv.z;
        Bs[b_k + 3][b_n] = bv.w;
        __syncthreads();

#pragma unroll
        for (int kk = 0; kk < TK; kk++) {
            float4 a0 = *(const float4*)&As[kk][ty * 8];
            float4 a1 = *(const float4*)&As[kk][ty * 8 + 4];
            float4 b  = *(const float4*)&Bs[kk][tx * 4];
            acc[0][0] += a0.x * b.x; acc[0][1] += a0.x * b.y; acc[0][2] += a0.x * b.z; acc[0][3] += a0.x * b.w;
            acc[1][0] += a0.y * b.x; acc[1][1] += a0.y * b.y; acc[1][2] += a0.y * b.z; acc[1][3] += a0.y * b.w;
            acc[2][0] += a0.z * b.x; acc[2][1] += a0.z * b.y; acc[2][2] += a0.z * b.z; acc[2][3] += a0.z * b.w;
            acc[3][0] += a0.w * b.x; acc[3][1] += a0.w * b.y; acc[3][2] += a0.w * b.z; acc[3][3] += a0.w * b.w;
            acc[4][0] += a1.x * b.x; acc[4][1] += a1.x * b.y; acc[4][2] += a1.x * b.z; acc[4][3] += a1.x * b.w;
            acc[5][0] += a1.y * b.x; acc[5][1] += a1.y * b.y; acc[5][2] += a1.y * b.z; acc[5][3] += a1.y * b.w;
            acc[6][0] += a1.z * b.x; acc[6][1] += a1.z * b.y; acc[6][2] += a1.z * b.z; acc[6][3] += a1.z * b.w;
            acc[7][0] += a1.w * b.x; acc[7][1] += a1.w * b.y; acc[7][2] += a1.w * b.z; acc[7][3] += a1.w * b.w;
        }
        __syncthreads();
    }

#pragma unroll
    for (int i = 0; i < 8; i++) {
        int r = ty * 8 + i;
        int tok = toks[r];
        if (tok < 0) continue;
        float4 v = make_float4(acc[i][0], acc[i][1], acc[i][2], acc[i][3]);
        *(float4*)(out + (size_t)tok * DIM + n0 + tx * 4) = v;
    }
}

// ---------------------------------------------------------------------------
extern "C" void kernel_launch(void* const* d_in, const int* in_sizes, int n_in,
                              void* d_out, int out_size) {
    const float* x    = (const float*)d_in[0];
    const float* rw   = (const float*)d_in[1];
    const float* fc   = (const float*)d_in[2];
    const float* proj = (const float*)d_in[3];
    float* out = (float*)d_out;

    init_counts_kernel<<<1, 32>>>();
    router_kernel<<<(NTOK * 32) / 256, 256>>>(x, rw);

    dim3 g1(HDIM / TN, NTOK / TM, NE);   // 64 x 32 x 8, most blocks early-exit
    gemm1_kernel<<<g1, 256>>>(x, fc);

    dim3 g2(DIM / TN, NTOK / TM, NE);    // 16 x 32 x 8
    gemm2_kernel<<<g2, 256>>>(proj, out);
}